// round 7
// baseline (speedup 1.0000x reference)
#include <cuda_runtime.h>
#include <cstdint>
#include <math.h>

// ---------------------------------------------------------------------------
// LOUPE sampler, fully fused mask computation + bandwidth-bound apply.
//   mask_kernel (1 block, 1024 thr): sigmoid -> rescale -> means ->
//     32 parallel rejection-sampling candidates (warp-per-candidate) with the
//     threefry split chain streamed in via smem flags -> select first accept.
//   apply_mask_kernel: broadcast multiply, 4x float4 per thread, streaming.
// Output: [masked_kspace 256*2*320*320 f32][mask_full 256*1*320*320 f32]
// ---------------------------------------------------------------------------

#define SLOPE 5.0f
#define LN 320
#define NPROBE 32

__device__ float d_mask[LN];

// --- threefry2x32, 20 rounds (JAX) ---
__device__ __forceinline__ uint32_t rotl32(uint32_t v, int d) {
    return (v << d) | (v >> (32 - d));
}

__device__ __forceinline__ void threefry2x32(uint32_t k0, uint32_t k1,
                                             uint32_t c0, uint32_t c1,
                                             uint32_t& o0, uint32_t& o1) {
    uint32_t k2 = k0 ^ k1 ^ 0x1BD11BDAu;
    uint32_t x0 = c0 + k0;
    uint32_t x1 = c1 + k1;
#define TF_ROUND(r) { x0 += x1; x1 = rotl32(x1, (r)); x1 ^= x0; }
    TF_ROUND(13) TF_ROUND(15) TF_ROUND(26) TF_ROUND(6)
    x0 += k1; x1 += k2 + 1u;
    TF_ROUND(17) TF_ROUND(29) TF_ROUND(16) TF_ROUND(24)
    x0 += k2; x1 += k0 + 2u;
    TF_ROUND(13) TF_ROUND(15) TF_ROUND(26) TF_ROUND(6)
    x0 += k0; x1 += k1 + 3u;
    TF_ROUND(17) TF_ROUND(29) TF_ROUND(16) TF_ROUND(24)
    x0 += k1; x1 += k2 + 4u;
    TF_ROUND(13) TF_ROUND(15) TF_ROUND(26) TF_ROUND(6)
    x0 += k2; x1 += k0 + 5u;
#undef TF_ROUND
    o0 = x0; o1 = x1;
}

__device__ __forceinline__ float bits_to_uniform(uint32_t b) {
    return __uint_as_float((b >> 9) | 0x3f800000u) - 1.0f;
}

#define BAR_SUBSET(id, cnt) asm volatile("bar.sync %0, %1;" :: "r"(id), "r"(cnt) : "memory")

// ---------------------------------------------------------------------------
// Fused mask kernel. 1 block x 1024 threads (32 warps):
//   warps 0-9  : per-line math (sigmoid, rescale) on lines tid<320
//   warp  10   : warp-parallel mean reductions, publishes xflag
//   warp 11 l0 : threefry split chain, publishes subs[i] incrementally
//   warp  w    : candidate w draws (once subs[w] + xflag ready)
// JAX partitionable threefry:
//   split(key):  new = TF(key,0,0), sub = TF(key,0,1)
//   bits(key,i): x0 ^ x1 of TF(key, 0, i)
// ---------------------------------------------------------------------------
__global__ void __launch_bounds__(1024) mask_kernel(
    const float* __restrict__ logits, const float* __restrict__ sparsity_p) {
    __shared__ float xs[LN];
    __shared__ float sh_xbar, sh_xm;
    __shared__ uint2 subs[NPROBE];
    __shared__ uint2 sh_chain_key;
    __shared__ int   cnt[NPROBE];
    __shared__ uint32_t words[NPROBE][10];
    volatile __shared__ int subflag[NPROBE];
    volatile __shared__ int xflag;
    __shared__ int sh_sel;

    const int tid  = threadIdx.x;
    const int wid  = tid >> 5;
    const int lane = tid & 31;

    if (tid < NPROBE) { subflag[tid] = 0; cnt[tid] = 0; }
    if (tid == NPROBE) xflag = 0;
    __syncthreads();

    // ---- chain builder (warp 11, lane 0), overlapped with everything ----
    if (wid == 11) {
        if (lane == 0) {
            uint32_t k0 = 0u, k1 = 42u;   // jax.random.key(42)
            for (int i = 0; i < NPROBE; i++) {
                uint32_t s0, s1, n0, n1;
                threefry2x32(k0, k1, 0u, 1u, s0, s1);   // sub_i
                threefry2x32(k0, k1, 0u, 0u, n0, n1);   // key_{i+1}
                subs[i] = make_uint2(s0, s1);
                __threadfence_block();
                subflag[i] = 1;
                k0 = n0; k1 = n1;
            }
            sh_chain_key = make_uint2(k0, k1);          // key after NPROBE splits
        }
        __syncwarp();
    }

    // ---- per-line math + means (warps 0-10, named barrier 1, 352 thr) ----
    float x_line = 0.0f;
    if (wid <= 10) {
        float s = 0.0f;
        if (tid < LN) {
            s = 1.0f / (1.0f + expf(-SLOPE * logits[tid]));
            xs[tid] = s;
        }
        BAR_SUBSET(1, 352);
        if (wid == 10) {   // xbar: warp-parallel sum of 320 values
            float a = 0.0f;
            for (int i = lane; i < LN; i += 32) a += xs[i];
            for (int o = 16; o > 0; o >>= 1) a += __shfl_down_sync(0xffffffffu, a, o);
            if (lane == 0) sh_xbar = a / (float)LN;
        }
        BAR_SUBSET(1, 352);
        if (tid < LN) {
            const float sparsity = *sparsity_p;
            const float xbar = sh_xbar;
            const float r = sparsity / xbar;
            const float beta = (1.0f - sparsity) / (1.0f - xbar);
            x_line = (r <= 1.0f) ? (s * r) : (1.0f - (1.0f - s) * beta);
            xs[tid] = x_line;
        }
        BAR_SUBSET(1, 352);
        if (wid == 10) {   // xm
            float a = 0.0f;
            for (int i = lane; i < LN; i += 32) a += xs[i];
            for (int o = 16; o > 0; o >>= 1) a += __shfl_down_sync(0xffffffffu, a, o);
            if (lane == 0) {
                sh_xm = a / (float)LN;
                __threadfence_block();
                xflag = 1;
            }
        }
    }

    // ---- draw phase: warp w evaluates candidate w ----
    while (xflag == 0) { }
    while (subflag[wid] == 0) { }
    __threadfence_block();

    {
        const uint2 sub = subs[wid];
        int c = 0;
        #pragma unroll
        for (int k = 0; k < 10; k++) {
            const int j = k * 32 + lane;
            uint32_t u, v;
            threefry2x32(sub.x, sub.y, 0u, (uint32_t)j, u, v);
            const float p = bits_to_uniform(u ^ v);
            const int pred = xs[j] > p;
            const uint32_t b = __ballot_sync(0xffffffffu, pred);
            if (lane == k) words[wid][k] = b;
            c += __popc(b);
        }
        if (lane == 0) cnt[wid] = c;
    }
    __syncthreads();

    // ---- selection ----
    const float xm  = sh_xm;
    const float tol = 1e-3f + 1e-5f * fabsf(xm);
    if (tid == 0) {
        int sel = -1;
        for (int i = 0; i < NPROBE; i++) {
            float m = (float)cnt[i] / (float)LN;
            if (fabsf(m - xm) <= tol) { sel = i; break; }
        }
        sh_sel = sel;
    }
    __syncthreads();
    const int sel = sh_sel;

    if (sel >= 0) {
        if (tid < LN) {
            uint32_t w = words[sel][tid >> 5];
            float v = ((w >> (tid & 31)) & 1u) ? 1.0f : 0.0f;
            if (tid == 0 || tid == LN - 1) v = 1.0f;
            d_mask[tid] = v;
        }
        return;
    }

    // ---- fallback (rare): continue sequential chain from key_NPROBE ----
    __shared__ uint32_t key0, key1, sub0, sub1;
    if (tid == 0) { key0 = sh_chain_key.x; key1 = sh_chain_key.y; }
    __syncthreads();
    const float x = (tid < LN) ? xs[tid] : 0.0f;
    bool res = false;
    for (int iter = 0; iter < 100000; ++iter) {
        if (tid == 0) {
            uint32_t nk0, nk1, ns0, ns1;
            threefry2x32(key0, key1, 0u, 0u, nk0, nk1);
            threefry2x32(key0, key1, 0u, 1u, ns0, ns1);
            key0 = nk0; key1 = nk1;
            sub0 = ns0; sub1 = ns1;
        }
        __syncthreads();
        bool r2 = false;
        if (tid < LN) {
            uint32_t u, v;
            threefry2x32(sub0, sub1, 0u, (uint32_t)tid, u, v);
            r2 = x > bits_to_uniform(u ^ v);
        }
        res = r2;
        int c = __syncthreads_count((tid < LN && res) ? 1 : 0);
        float m = (float)c / (float)LN;
        if (fabsf(m - xm) <= tol) break;
    }
    if (tid < LN) {
        float v = res ? 1.0f : 0.0f;
        if (tid == 0 || tid == LN - 1) v = 1.0f;
        d_mask[tid] = v;
    }
}

// ---------------------------------------------------------------------------
// B: out[0:n4m) = kspace * mask[h] ; out[n4m:n4tot) = mask[h] broadcast.
//    4 float4 per thread (64B), streaming hints, front-batched loads.
// ---------------------------------------------------------------------------
__global__ void __launch_bounds__(256) apply_mask_kernel(
    const float4* __restrict__ ksp, float4* __restrict__ out,
    int n4m, int n4tot) {
    int base = (blockIdx.x * blockDim.x + threadIdx.x) * 4;
    if (base >= n4tot) return;

    if (base + 3 < n4m) {            // fully inside masked_kspace region
        float4 a0 = __ldcs(&ksp[base + 0]);
        float4 a1 = __ldcs(&ksp[base + 1]);
        float4 a2 = __ldcs(&ksp[base + 2]);
        float4 a3 = __ldcs(&ksp[base + 3]);
        #pragma unroll
        for (int e = 0; e < 4; e++) {
            int idx = base + e;
            float m = d_mask[(idx / 80) % LN];
            float4 a = (e == 0) ? a0 : (e == 1) ? a1 : (e == 2) ? a2 : a3;
            a.x *= m; a.y *= m; a.z *= m; a.w *= m;
            __stcs(&out[idx], a);
        }
    } else {
        #pragma unroll
        for (int e = 0; e < 4; e++) {
            int idx = base + e;
            if (idx >= n4tot) break;
            if (idx < n4m) {
                float m = d_mask[(idx / 80) % LN];
                float4 a = __ldcs(&ksp[idx]);
                a.x *= m; a.y *= m; a.z *= m; a.w *= m;
                __stcs(&out[idx], a);
            } else {
                float m = d_mask[((idx - n4m) / 80) % LN];
                __stcs(&out[idx], make_float4(m, m, m, m));
            }
        }
    }
}

extern "C" void kernel_launch(void* const* d_in, const int* in_sizes, int n_in,
                              void* d_out, int out_size) {
    const float* kspace   = (const float*)d_in[0];  // (256,2,320,320)
    const float* sparsity = (const float*)d_in[1];  // scalar
    const float* logits   = (const float*)d_in[2];  // (320,)

    mask_kernel<<<1, 1024>>>(logits, sparsity);

    int n4m   = in_sizes[0] / 4;
    int n4tot = out_size / 4;
    int threads = 256;
    int blocks = (n4tot / 4 + threads - 1) / threads;
    apply_mask_kernel<<<blocks, threads>>>(
        (const float4*)kspace, (float4*)d_out, n4m, n4tot);
}

// round 8
// speedup vs baseline: 1.8534x; 1.8534x over previous
#include <cuda_runtime.h>
#include <cstdint>
#include <math.h>

// ---------------------------------------------------------------------------
// LOUPE sampler.
//  Host: threefry split-chain (data-independent) -> 32 candidate sub-keys
//        passed as kernel params.
//  probe_kernel   : 32 blocks, one rejection-sampling candidate each
//                   (redundant tiny prep per block; no inter-kernel deps).
//  finalize_kernel: pick first accepted candidate -> d_mask (seq. fallback).
//  apply_mask     : bandwidth kernel; skips LOADS on zero-mask lines
//                   (75% of read traffic eliminated).
// Output: [masked_kspace 256*2*320*320 f32][mask_full 256*1*320*320 f32]
// ---------------------------------------------------------------------------

#define SLOPE 5.0f
#define LN 320
#define NPROBE 32

struct SubKeys {
    uint2 s[NPROBE];   // sub-key for candidate i
    uint2 tail;        // key state after NPROBE splits (fallback chain)
};

__device__ float    d_mask[LN];
__device__ float    d_xs[LN];
__device__ float    d_xm;
__device__ int      d_cnt[NPROBE];
__device__ uint32_t d_words[NPROBE][10];

// --- threefry2x32, 20 rounds (JAX), host+device ---
__host__ __device__ __forceinline__ uint32_t rotl32(uint32_t v, int d) {
    return (v << d) | (v >> (32 - d));
}

__host__ __device__ __forceinline__ void threefry2x32(
    uint32_t k0, uint32_t k1, uint32_t c0, uint32_t c1,
    uint32_t& o0, uint32_t& o1) {
    uint32_t k2 = k0 ^ k1 ^ 0x1BD11BDAu;
    uint32_t x0 = c0 + k0;
    uint32_t x1 = c1 + k1;
#define TF_ROUND(r) { x0 += x1; x1 = rotl32(x1, (r)); x1 ^= x0; }
    TF_ROUND(13) TF_ROUND(15) TF_ROUND(26) TF_ROUND(6)
    x0 += k1; x1 += k2 + 1u;
    TF_ROUND(17) TF_ROUND(29) TF_ROUND(16) TF_ROUND(24)
    x0 += k2; x1 += k0 + 2u;
    TF_ROUND(13) TF_ROUND(15) TF_ROUND(26) TF_ROUND(6)
    x0 += k0; x1 += k1 + 3u;
    TF_ROUND(17) TF_ROUND(29) TF_ROUND(16) TF_ROUND(24)
    x0 += k1; x1 += k2 + 4u;
    TF_ROUND(13) TF_ROUND(15) TF_ROUND(26) TF_ROUND(6)
    x0 += k2; x1 += k0 + 5u;
#undef TF_ROUND
    o0 = x0; o1 = x1;
}

__device__ __forceinline__ float bits_to_uniform(uint32_t b) {
    return __uint_as_float((b >> 9) | 0x3f800000u) - 1.0f;
}

// ---------------------------------------------------------------------------
// probe: 32 blocks x 320 threads. Block b evaluates candidate b.
// Each block redundantly computes sigmoid/rescale/means (cheap, removes
// inter-kernel data deps beyond logits/sparsity).
// JAX partitionable threefry: bits(key,i) = x0^x1 of TF(key, 0, i).
// ---------------------------------------------------------------------------
__global__ void __launch_bounds__(LN) probe_kernel(
    const float* __restrict__ logits, const float* __restrict__ sparsity_p,
    SubKeys subs) {
    __shared__ float xs[LN];
    __shared__ float wsum[10];
    __shared__ float sh_xbar, sh_xm;

    const int tid  = threadIdx.x;
    const int wid  = tid >> 5;
    const int lane = tid & 31;
    const int b    = blockIdx.x;

    float s = 1.0f / (1.0f + expf(-SLOPE * logits[tid]));
    xs[tid] = s;

    // block reduce: xbar
    float a = s;
    for (int o = 16; o > 0; o >>= 1) a += __shfl_down_sync(0xffffffffu, a, o);
    if (lane == 0) wsum[wid] = a;
    __syncthreads();
    if (wid == 0) {
        float t = (lane < 10) ? wsum[lane] : 0.0f;
        for (int o = 8; o > 0; o >>= 1) t += __shfl_down_sync(0xffffffffu, t, o);
        if (lane == 0) sh_xbar = t / (float)LN;
    }
    __syncthreads();

    // rescale
    const float sparsity = *sparsity_p;
    const float xbar = sh_xbar;
    const float r = sparsity / xbar;
    const float beta = (1.0f - sparsity) / (1.0f - xbar);
    const float x = (r <= 1.0f) ? (s * r) : (1.0f - (1.0f - s) * beta);

    // block reduce: xm
    a = x;
    for (int o = 16; o > 0; o >>= 1) a += __shfl_down_sync(0xffffffffu, a, o);
    if (lane == 0) wsum[wid] = a;
    __syncthreads();
    if (wid == 0) {
        float t = (lane < 10) ? wsum[lane] : 0.0f;
        for (int o = 8; o > 0; o >>= 1) t += __shfl_down_sync(0xffffffffu, t, o);
        if (lane == 0) sh_xm = t / (float)LN;
    }

    if (b == 0) d_xs[tid] = x;           // for finalize fallback
    if (b == 0 && tid == 0) { /* written below after sync */ }

    // draw candidate b
    const uint2 sub = subs.s[b];
    uint32_t u, v;
    threefry2x32(sub.x, sub.y, 0u, (uint32_t)tid, u, v);
    const int pred = x > bits_to_uniform(u ^ v);

    const uint32_t w = __ballot_sync(0xffffffffu, pred);
    if (lane == 0) d_words[b][wid] = w;

    const int c = __syncthreads_count(pred);
    if (tid == 0) {
        d_cnt[b] = c;
        if (b == 0) d_xm = sh_xm;
    }
}

// ---------------------------------------------------------------------------
// finalize: 1 block x 320. First accepted candidate -> d_mask.
// Fallback: continue sequential rejection loop from subs.tail (rare).
// ---------------------------------------------------------------------------
__global__ void __launch_bounds__(LN) finalize_kernel(SubKeys subs) {
    __shared__ int sh_sel;
    __shared__ uint32_t key0, key1, sub0, sub1;

    const int tid = threadIdx.x;
    const float xm = d_xm;
    const float tol = 1e-3f + 1e-5f * fabsf(xm);

    if (tid == 0) {
        int sel = -1;
        for (int i = 0; i < NPROBE; i++) {
            float m = (float)d_cnt[i] / (float)LN;
            if (fabsf(m - xm) <= tol) { sel = i; break; }
        }
        sh_sel = sel;
        if (sel < 0) { key0 = subs.tail.x; key1 = subs.tail.y; }
    }
    __syncthreads();
    const int sel = sh_sel;

    float vout;
    if (sel >= 0) {
        uint32_t w = d_words[sel][tid >> 5];
        vout = ((w >> (tid & 31)) & 1u) ? 1.0f : 0.0f;
    } else {
        const float x = d_xs[tid];
        bool res = false;
        for (int iter = 0; iter < 100000; ++iter) {
            if (tid == 0) {   // split(key): new=TF(key,0,0), sub=TF(key,0,1)
                uint32_t nk0, nk1, ns0, ns1;
                threefry2x32(key0, key1, 0u, 0u, nk0, nk1);
                threefry2x32(key0, key1, 0u, 1u, ns0, ns1);
                key0 = nk0; key1 = nk1;
                sub0 = ns0; sub1 = ns1;
            }
            __syncthreads();
            uint32_t u, v;
            threefry2x32(sub0, sub1, 0u, (uint32_t)tid, u, v);
            res = x > bits_to_uniform(u ^ v);
            int c = __syncthreads_count(res ? 1 : 0);
            float m = (float)c / (float)LN;
            if (fabsf(m - xm) <= tol) break;
        }
        vout = res ? 1.0f : 0.0f;
    }

    if (tid == 0 || tid == LN - 1) vout = 1.0f;
    d_mask[tid] = vout;
}

// ---------------------------------------------------------------------------
// B: out[0:n4m) = kspace * mask[h] ; out[n4m:n4tot) = mask[h] broadcast.
//    1 float4 / thread (fully coalesced). Zero-mask lines are written as
//    zeros WITHOUT loading kspace (kills 75% of read traffic).
// ---------------------------------------------------------------------------
__global__ void __launch_bounds__(256) apply_mask_kernel(
    const float4* __restrict__ ksp, float4* __restrict__ out,
    int n4m, int n4tot) {
    int idx = blockIdx.x * blockDim.x + threadIdx.x;
    if (idx >= n4tot) return;
    if (idx < n4m) {
        int row = idx / 80;            // row of 320 floats (W=320 -> 80 float4)
        float m = d_mask[row % LN];    // exactly 0.0f or 1.0f
        if (m != 0.0f) {
            __stcs(&out[idx], __ldcs(&ksp[idx]));
        } else {
            __stcs(&out[idx], make_float4(0.f, 0.f, 0.f, 0.f));
        }
    } else {
        int row = (idx - n4m) / 80;
        float m = d_mask[row % LN];
        __stcs(&out[idx], make_float4(m, m, m, m));
    }
}

extern "C" void kernel_launch(void* const* d_in, const int* in_sizes, int n_in,
                              void* d_out, int out_size) {
    const float* kspace   = (const float*)d_in[0];  // (256,2,320,320)
    const float* sparsity = (const float*)d_in[1];  // scalar
    const float* logits   = (const float*)d_in[2];  // (320,)

    // Host-side threefry split chain (data-independent of device inputs).
    // JAX partitionable split: new_key = TF(key,0,0), sub = TF(key,0,1).
    SubKeys subs;
    {
        uint32_t k0 = 0u, k1 = 42u;   // jax.random.key(42)
        for (int i = 0; i < NPROBE; i++) {
            uint32_t s0, s1, n0, n1;
            threefry2x32(k0, k1, 0u, 1u, s0, s1);
            threefry2x32(k0, k1, 0u, 0u, n0, n1);
            subs.s[i] = make_uint2(s0, s1);
            k0 = n0; k1 = n1;
        }
        subs.tail = make_uint2(k0, k1);
    }

    probe_kernel<<<NPROBE, LN>>>(logits, sparsity, subs);
    finalize_kernel<<<1, LN>>>(subs);

    int n4m   = in_sizes[0] / 4;
    int n4tot = out_size / 4;
    int threads = 256;
    int blocks = (n4tot + threads - 1) / threads;
    apply_mask_kernel<<<blocks, threads>>>(
        (const float4*)kspace, (float4*)d_out, n4m, n4tot);
}

// round 9
// speedup vs baseline: 1.8590x; 1.0030x over previous
#include <cuda_runtime.h>
#include <cstdint>
#include <math.h>

// ---------------------------------------------------------------------------
// LOUPE sampler.
//  Host: threefry split-chain (data-independent) -> 32 candidate sub-keys.
//  mask_kernel : 32 blocks, one rejection-sampling candidate each; the LAST
//                block (ticket) selects the first accepted candidate and
//                emits d_mask (sequential fallback if none accept).
//  apply_mask  : bandwidth kernel; skips loads on zero-mask lines.
// Output: [masked_kspace 256*2*320*320 f32][mask_full 256*1*320*320 f32]
// ---------------------------------------------------------------------------

#define SLOPE 5.0f
#define LN 320
#define NPROBE 32

struct SubKeys {
    uint2 s[NPROBE];   // sub-key for candidate i
    uint2 tail;        // key state after NPROBE splits (fallback chain)
};

__device__ float    d_mask[LN];
__device__ int      d_cnt[NPROBE];
__device__ uint32_t d_words[NPROBE][10];
__device__ int      d_ticket = 0;     // reset by finalizer each run

// --- threefry2x32, 20 rounds (JAX), host+device ---
__host__ __device__ __forceinline__ uint32_t rotl32(uint32_t v, int d) {
    return (v << d) | (v >> (32 - d));
}

__host__ __device__ __forceinline__ void threefry2x32(
    uint32_t k0, uint32_t k1, uint32_t c0, uint32_t c1,
    uint32_t& o0, uint32_t& o1) {
    uint32_t k2 = k0 ^ k1 ^ 0x1BD11BDAu;
    uint32_t x0 = c0 + k0;
    uint32_t x1 = c1 + k1;
#define TF_ROUND(r) { x0 += x1; x1 = rotl32(x1, (r)); x1 ^= x0; }
    TF_ROUND(13) TF_ROUND(15) TF_ROUND(26) TF_ROUND(6)
    x0 += k1; x1 += k2 + 1u;
    TF_ROUND(17) TF_ROUND(29) TF_ROUND(16) TF_ROUND(24)
    x0 += k2; x1 += k0 + 2u;
    TF_ROUND(13) TF_ROUND(15) TF_ROUND(26) TF_ROUND(6)
    x0 += k0; x1 += k1 + 3u;
    TF_ROUND(17) TF_ROUND(29) TF_ROUND(16) TF_ROUND(24)
    x0 += k1; x1 += k2 + 4u;
    TF_ROUND(13) TF_ROUND(15) TF_ROUND(26) TF_ROUND(6)
    x0 += k2; x1 += k0 + 5u;
#undef TF_ROUND
    o0 = x0; o1 = x1;
}

__device__ __forceinline__ float bits_to_uniform(uint32_t b) {
    return __uint_as_float((b >> 9) | 0x3f800000u) - 1.0f;
}

// ---------------------------------------------------------------------------
// mask_kernel: 32 blocks x 320 threads. Block b evaluates candidate b, the
// last block to finish (device atomic ticket) performs selection + emission.
// JAX partitionable threefry: bits(key,i) = x0^x1 of TF(key, 0, i).
// ---------------------------------------------------------------------------
__global__ void __launch_bounds__(LN) mask_kernel(
    const float* __restrict__ logits, const float* __restrict__ sparsity_p,
    SubKeys subs) {
    __shared__ float xs[LN];
    __shared__ float wsum[10];
    __shared__ float sh_xbar, sh_xm;
    __shared__ int   sh_last, sh_sel;

    const int tid  = threadIdx.x;
    const int wid  = tid >> 5;
    const int lane = tid & 31;
    const int b    = blockIdx.x;

    float s = 1.0f / (1.0f + expf(-SLOPE * logits[tid]));

    // block reduce: xbar
    float a = s;
    for (int o = 16; o > 0; o >>= 1) a += __shfl_down_sync(0xffffffffu, a, o);
    if (lane == 0) wsum[wid] = a;
    __syncthreads();
    if (wid == 0) {
        float t = (lane < 10) ? wsum[lane] : 0.0f;
        for (int o = 8; o > 0; o >>= 1) t += __shfl_down_sync(0xffffffffu, t, o);
        if (lane == 0) sh_xbar = t / (float)LN;
    }
    __syncthreads();

    // rescale
    const float sparsity = __ldg(sparsity_p);
    const float xbar = sh_xbar;
    const float r = sparsity / xbar;
    const float beta = (1.0f - sparsity) / (1.0f - xbar);
    const float x = (r <= 1.0f) ? (s * r) : (1.0f - (1.0f - s) * beta);
    xs[tid] = x;

    // block reduce: xm
    a = x;
    for (int o = 16; o > 0; o >>= 1) a += __shfl_down_sync(0xffffffffu, a, o);
    if (lane == 0) wsum[wid] = a;
    __syncthreads();
    if (wid == 0) {
        float t = (lane < 10) ? wsum[lane] : 0.0f;
        for (int o = 8; o > 0; o >>= 1) t += __shfl_down_sync(0xffffffffu, t, o);
        if (lane == 0) sh_xm = t / (float)LN;
    }

    // draw candidate b
    const uint2 sub = subs.s[b];
    uint32_t u, v;
    threefry2x32(sub.x, sub.y, 0u, (uint32_t)tid, u, v);
    const int pred = x > bits_to_uniform(u ^ v);

    const uint32_t w = __ballot_sync(0xffffffffu, pred);
    if (lane == 0) d_words[b][wid] = w;

    const int c = __syncthreads_count(pred);   // also orders sh_xm/xs for all
    if (tid == 0) d_cnt[b] = c;

    // ---- last-block ticket: finalizer ----
    if (tid == 0) {
        __threadfence();                       // publish d_words/d_cnt
        int t = atomicAdd(&d_ticket, 1);
        sh_last = (t == NPROBE - 1) ? 1 : 0;
        if (sh_last) d_ticket = 0;             // reset for next graph replay
    }
    __syncthreads();
    if (!sh_last) return;

    // selection (all 32 candidates' counts are globally visible now)
    const float xm  = sh_xm;
    const float tol = 1e-3f + 1e-5f * fabsf(xm);
    if (tid == 0) {
        int sel = -1;
        for (int i = 0; i < NPROBE; i++) {
            float m = (float)(*(volatile int*)&d_cnt[i]) / (float)LN;
            if (fabsf(m - xm) <= tol) { sel = i; break; }
        }
        sh_sel = sel;
    }
    __syncthreads();
    const int sel = sh_sel;

    float vout;
    if (sel >= 0) {
        uint32_t ww = *(volatile uint32_t*)&d_words[sel][wid];
        vout = ((ww >> lane) & 1u) ? 1.0f : 0.0f;
    } else {
        // fallback (rare): continue sequential split chain from subs.tail
        __shared__ uint32_t key0, key1, sub0, sub1;
        if (tid == 0) { key0 = subs.tail.x; key1 = subs.tail.y; }
        __syncthreads();
        bool res = false;
        for (int iter = 0; iter < 100000; ++iter) {
            if (tid == 0) {   // split(key): new=TF(key,0,0), sub=TF(key,0,1)
                uint32_t nk0, nk1, ns0, ns1;
                threefry2x32(key0, key1, 0u, 0u, nk0, nk1);
                threefry2x32(key0, key1, 0u, 1u, ns0, ns1);
                key0 = nk0; key1 = nk1;
                sub0 = ns0; sub1 = ns1;
            }
            __syncthreads();
            uint32_t uu, vv;
            threefry2x32(sub0, sub1, 0u, (uint32_t)tid, uu, vv);
            res = xs[tid] > bits_to_uniform(uu ^ vv);
            int cc = __syncthreads_count(res ? 1 : 0);
            float m = (float)cc / (float)LN;
            if (fabsf(m - xm) <= tol) break;
        }
        vout = res ? 1.0f : 0.0f;
    }

    if (tid == 0 || tid == LN - 1) vout = 1.0f;
    d_mask[tid] = vout;
}

// ---------------------------------------------------------------------------
// B: out[0:n4m) = kspace * mask[h] ; out[n4m:n4tot) = mask[h] broadcast.
//    1 float4 / thread (fully coalesced). Zero-mask lines are written as
//    zeros WITHOUT loading kspace.
// ---------------------------------------------------------------------------
__global__ void __launch_bounds__(256) apply_mask_kernel(
    const float4* __restrict__ ksp, float4* __restrict__ out,
    int n4m, int n4tot) {
    int idx = blockIdx.x * blockDim.x + threadIdx.x;
    if (idx >= n4tot) return;
    if (idx < n4m) {
        int row = idx / 80;            // row of 320 floats (W=320 -> 80 float4)
        float m = d_mask[row % LN];    // exactly 0.0f or 1.0f
        if (m != 0.0f) {
            __stcs(&out[idx], __ldcs(&ksp[idx]));
        } else {
            __stcs(&out[idx], make_float4(0.f, 0.f, 0.f, 0.f));
        }
    } else {
        int row = (idx - n4m) / 80;
        float m = d_mask[row % LN];
        __stcs(&out[idx], make_float4(m, m, m, m));
    }
}

extern "C" void kernel_launch(void* const* d_in, const int* in_sizes, int n_in,
                              void* d_out, int out_size) {
    const float* kspace   = (const float*)d_in[0];  // (256,2,320,320)
    const float* sparsity = (const float*)d_in[1];  // scalar
    const float* logits   = (const float*)d_in[2];  // (320,)

    // Host-side threefry split chain (data-independent of device inputs).
    // JAX partitionable split: new_key = TF(key,0,0), sub = TF(key,0,1).
    SubKeys subs;
    {
        uint32_t k0 = 0u, k1 = 42u;   // jax.random.key(42)
        for (int i = 0; i < NPROBE; i++) {
            uint32_t s0, s1, n0, n1;
            threefry2x32(k0, k1, 0u, 1u, s0, s1);
            threefry2x32(k0, k1, 0u, 0u, n0, n1);
            subs.s[i] = make_uint2(s0, s1);
            k0 = n0; k1 = n1;
        }
        subs.tail = make_uint2(k0, k1);
    }

    mask_kernel<<<NPROBE, LN>>>(logits, sparsity, subs);

    int n4m   = in_sizes[0] / 4;
    int n4tot = out_size / 4;
    int threads = 256;
    int blocks = (n4tot + threads - 1) / threads;
    apply_mask_kernel<<<blocks, threads>>>(
        (const float4*)kspace, (float4*)d_out, n4m, n4tot);
}